// round 9
// baseline (speedup 1.0000x reference)
#include <cuda_runtime.h>
#include <math.h>
#include <stdint.h>

#define B 64
#define NK 2048
#define HID 1024
#define EMB 512
#define KEY 512
#define VOCAB 50257

#define O_OFF (B*VOCAB)
#define A_OFF (O_OFF + B*HID)

// ---------------- scratch ---------------------------------------------------
__device__ float g_qw[B*HID];
__device__ float g_scores[B*NK];
__device__ float g_x[B*(EMB+KEY)];
__device__ float g_h[B*HID];
__device__ float g_gi[B*3*HID];
__device__ float g_gh[B*3*HID];
__device__ float g_lse[B];
__device__ float g_pm[B*8];
__device__ float g_ps[B*8];
__device__ float g_wkR[KEY*HID];      // Wk tf32-rounded (RNA), [k][n]

__device__ __forceinline__ float to_tf32(float x) {
    unsigned r;
    asm("cvt.rna.tf32.f32 %0, %1;" : "=r"(r) : "f"(x));
    return __uint_as_float(r);
}
__device__ __forceinline__ uint32_t smem_u32(const void* p) {
    uint32_t a;
    asm("{ .reg .u64 t; cvta.to.shared.u64 t, %1; cvt.u32.u64 %0, t; }" : "=r"(a) : "l"(p));
    return a;
}

// ---------------- kernel: round Wk to tf32 ---------------------------------
__global__ void __launch_bounds__(256) k_wkr(const float* __restrict__ Wk) {
    int i = blockIdx.x * 256 + threadIdx.x;
    g_wkR[i] = to_tf32(Wk[i]);
}

// ---------------- kernel: qw = Q @ Wq + bk ---------------------------------
__global__ void __launch_bounds__(256) k_qw(const float* __restrict__ hidden,
                                            const float* __restrict__ Wq,
                                            const float* __restrict__ bk) {
    int h = blockIdx.x * 256 + threadIdx.x;
    int b = blockIdx.y;
    __shared__ float q_s[HID];
    for (int i = threadIdx.x; i < HID; i += 256) q_s[i] = hidden[b*HID + i];
    __syncthreads();
    float acc = bk[h];
    #pragma unroll 8
    for (int k = 0; k < HID; k++)
        acc = fmaf(q_s[k], Wq[(size_t)k*HID + h], acc);
    g_qw[b*HID + h] = acc;
}

// ---------------- feat GEMM: tf32 mma, 1024 threads, fragment-major A ------
// Block: 64 rows A-stationary. 128 its: ncc = it>>6 (512-col chunk of HID),
// kc = it&63 (8-k chunk). 32 warps: wm(2) x 32 rows, wn(16) x 32 cols, nt=4.
#define BLD 520
#define B_STG (8*BLD*4)                  // 16640 bytes
#define F_A   0
#define F_B   (64*512*4)                 // 131072
#define F_QW  (F_B + 4*B_STG)            // 197632
#define F_V   (F_QW + HID*4)
#define F_SC  (F_V + HID*4)
#define FEAT_SMEM (F_SC + 64*4)          // 206080

__global__ void __launch_bounds__(1024) k_feat8(const float* __restrict__ ann,
                                                const float* __restrict__ v_attn) {
    extern __shared__ char sm[];
    const uint32_t smb = smem_u32(sm);
    float* A_f  = (float*)(sm + F_A);
    float* qw_s = (float*)(sm + F_QW);
    float* v_s  = (float*)(sm + F_V);
    float* sc_s = (float*)(sm + F_SC);

    const int bx   = blockIdx.x;
    const int b    = bx >> 5;
    const int row0 = (bx & 31) * 64;
    const int tid  = threadIdx.x;
    const int lane = tid & 31;
    const int warp = tid >> 5;
    const int wm   = warp >> 4;       // 0..1  (32-row half)
    const int wn   = warp & 15;       // 0..15 (32-col slice of 512-chunk)
    const int g    = lane >> 2;       // 0..7
    const int qt   = lane & 3;        // 0..3

    for (int i = tid; i < HID; i += 1024) {
        qw_s[i] = g_qw[b*HID + i];
        v_s[i]  = v_attn[i];
    }
    if (tid < 64) sc_s[tid] = 0.f;

    // A tile load -> fragment-major, tf32-rounded (RNA). One-time.
    {
        const float4* src = (const float4*)(ann + ((size_t)b * NK + row0) * KEY);
        for (int i = tid; i < 64*128; i += 1024) {
            int r  = i >> 7;
            int k4 = i & 127;
            float4 v4 = src[i];
            v4.x = to_tf32(v4.x); v4.y = to_tf32(v4.y);
            v4.z = to_tf32(v4.z); v4.w = to_tf32(v4.w);
            int ko   = k4 >> 1;
            int half = k4 & 1;
            int rg   = r >> 4;
            int hi8  = (r >> 3) & 1;
            int gg   = r & 7;
            int slot = (half << 1) | hi8;
            float* base = A_f + (ko*4 + rg)*128;
            base[(gg*4 + 0)*4 + slot] = v4.x;
            base[(gg*4 + 1)*4 + slot] = v4.y;
            base[(gg*4 + 2)*4 + slot] = v4.z;
            base[(gg*4 + 3)*4 + slot] = v4.w;
        }
    }

    // stage: 8 k-rows x 512 n-cols of Wk (one float4 per thread)
    auto issue = [&](int it) {
        int ncc = it >> 6, kc = it & 63, buf = it & 3;
        const float* src = g_wkR + (size_t)(kc*8)*HID + ncc*512;
        int r = tid >> 7, c4 = tid & 127;
        uint32_t dst = smb + F_B + buf*B_STG + (uint32_t)(r*BLD + c4*4)*4;
        const float* s = src + (size_t)r*HID + c4*4;
        asm volatile("cp.async.cg.shared.global [%0], [%1], 16;" :: "r"(dst), "l"(s));
        asm volatile("cp.async.commit_group;" ::: "memory");
    };

    issue(0); issue(1); issue(2);

    float rs[2][2] = {{0.f,0.f},{0.f,0.f}};
    float acc[2][4][4];
    const int rgbase = wm*2;

    for (int it = 0; it < 128; it++) {
        const int buf = it & 3;
        const int kc  = it & 63;
        asm volatile("cp.async.wait_group 2;" ::: "memory");
        __syncthreads();

        if (kc == 0) {
            #pragma unroll
            for (int mt = 0; mt < 2; mt++)
                #pragma unroll
                for (int nt = 0; nt < 4; nt++)
                    #pragma unroll
                    for (int i = 0; i < 4; i++) acc[mt][nt][i] = 0.f;
        }

        const float* Bst = (const float*)(sm + F_B + buf*B_STG);

        // load all fragments for this 8-k chunk, then MMAs
        float4 af[2];
        unsigned bf[4][2];
        #pragma unroll
        for (int mt = 0; mt < 2; mt++)
            af[mt] = *(const float4*)(A_f + ((kc*4 + rgbase + mt)*32 + lane)*4);
        #pragma unroll
        for (int nt = 0; nt < 4; nt++) {
            int cn = wn*32 + nt*8 + g;
            bf[nt][0] = __float_as_uint(Bst[qt*BLD + cn]);
            bf[nt][1] = __float_as_uint(Bst[(qt+4)*BLD + cn]);
        }
        #pragma unroll
        for (int nt = 0; nt < 4; nt++) {
            #pragma unroll
            for (int mt = 0; mt < 2; mt++) {
                asm volatile(
                    "mma.sync.aligned.m16n8k8.row.col.f32.tf32.tf32.f32 "
                    "{%0,%1,%2,%3}, {%4,%5,%6,%7}, {%8,%9}, {%0,%1,%2,%3};"
                    : "+f"(acc[mt][nt][0]), "+f"(acc[mt][nt][1]),
                      "+f"(acc[mt][nt][2]), "+f"(acc[mt][nt][3])
                    : "r"(__float_as_uint(af[mt].x)),
                      "r"(__float_as_uint(af[mt].y)),
                      "r"(__float_as_uint(af[mt].z)),
                      "r"(__float_as_uint(af[mt].w)),
                      "r"(bf[nt][0]), "r"(bf[nt][1]));
            }
        }

        if (kc == 63) {
            const int ncc = it >> 6;
            #pragma unroll
            for (int mt = 0; mt < 2; mt++)
                #pragma unroll
                for (int nt = 0; nt < 4; nt++) {
                    int h0 = ncc*512 + wn*32 + nt*8 + qt*2;
                    float v0 = v_s[h0],     q0u = qw_s[h0];
                    float v1 = v_s[h0 + 1], q1u = qw_s[h0 + 1];
                    rs[mt][0] = fmaf(v0, tanhf(acc[mt][nt][0] + q0u), rs[mt][0]);
                    rs[mt][0] = fmaf(v1, tanhf(acc[mt][nt][1] + q1u), rs[mt][0]);
                    rs[mt][1] = fmaf(v0, tanhf(acc[mt][nt][2] + q0u), rs[mt][1]);
                    rs[mt][1] = fmaf(v1, tanhf(acc[mt][nt][3] + q1u), rs[mt][1]);
                }
        }

        if (it + 3 < 128) issue(it + 3);
    }

    #pragma unroll
    for (int mt = 0; mt < 2; mt++)
        #pragma unroll
        for (int up = 0; up < 2; up++) {
            float p = rs[mt][up];
            p += __shfl_xor_sync(0xffffffffu, p, 1);
            p += __shfl_xor_sync(0xffffffffu, p, 2);
            if (qt == 0)
                atomicAdd(&sc_s[wm*32 + mt*16 + up*8 + g], p);
        }
    __syncthreads();
    if (tid < 64) g_scores[(size_t)b*NK + row0 + tid] = sc_s[tid];
}

// ---------------- softmax + emb copy ---------------------------------------
__global__ void __launch_bounds__(256) k_attn_sm(const int* __restrict__ ids,
                                                 const float* __restrict__ emb_table,
                                                 float* __restrict__ a_out) {
    int b = blockIdx.x;
    int tid = threadIdx.x;
    __shared__ float sc[NK];
    __shared__ float red[256];

    float m = -1e30f;
    for (int i = tid; i < NK; i += 256) {
        float v = g_scores[b*NK + i];
        sc[i] = v;
        m = fmaxf(m, v);
    }
    red[tid] = m; __syncthreads();
    for (int s = 128; s; s >>= 1) { if (tid < s) red[tid] = fmaxf(red[tid], red[tid+s]); __syncthreads(); }
    m = red[0]; __syncthreads();

    float sum = 0.f;
    for (int i = tid; i < NK; i += 256) { float e = expf(sc[i] - m); sc[i] = e; sum += e; }
    red[tid] = sum; __syncthreads();
    for (int s = 128; s; s >>= 1) { if (tid < s) red[tid] += red[tid+s]; __syncthreads(); }
    float inv = 1.f / red[0];
    __syncthreads();

    for (int i = tid; i < NK; i += 256)
        a_out[(size_t)b*NK + i] = sc[i] * inv;

    int id = ids[b];
    for (int k = tid; k < EMB; k += 256)
        g_x[b*(EMB+KEY) + k] = emb_table[(size_t)id*EMB + k];
}

// ---------------- context = a . ann ----------------------------------------
__global__ void __launch_bounds__(256) k_ctx(const float* __restrict__ ann,
                                             const float* __restrict__ a_out) {
    int b = blockIdx.x;
    int p = blockIdx.y;
    int tid = threadIdx.x;
    int c  = tid & 63;
    int rg = tid >> 6;
    __shared__ float part[4][64];

    const float* ab = ann + (size_t)b*NK*KEY + p*64 + c;
    const float* av = a_out + (size_t)b*NK;
    float acc = 0.f;
    for (int n = rg; n < NK; n += 4)
        acc = fmaf(av[n], ab[(size_t)n*KEY], acc);
    part[rg][c] = acc;
    __syncthreads();
    if (rg == 0)
        g_x[b*(EMB+KEY) + EMB + p*64 + c] =
            part[0][c] + part[1][c] + part[2][c] + part[3][c];
}

// ---------------- shared tf32 GEMM body (RNA-rounded fragments) ------------
#define L_ALD 68
#define L_BLD 68
#define L_ASTG (64*L_ALD*4)
#define L_BSTG (128*L_BLD*4)
#define L_STG  (L_ASTG + L_BSTG)
#define LOG_SMEM (3*L_STG)               // 156672

__device__ __forceinline__ void gemm_tc_body(const float* __restrict__ Amat,
                                             const float* __restrict__ W,
                                             int v0, int N, uint32_t smb, char* sm,
                                             float acc[2][4][4]) {
    const int tid = threadIdx.x;
    const int lane = tid & 31;
    const int warp = tid >> 5;
    const int wm = warp >> 2;
    const int wn = warp & 3;
    const int g  = lane >> 2;
    const int qt = lane & 3;

    auto issue = [&](int kc) {
        int buf = kc % 3;
        {
            const float* src = Amat + kc*64;
            #pragma unroll
            for (int u = 0; u < 4; u++) {
                int gi = tid + u*256;
                int r = gi >> 4, c4 = gi & 15;
                uint32_t dst = smb + buf*L_STG + (uint32_t)(r*L_ALD + c4*4)*4;
                const float* s = src + (size_t)r*HID + c4*4;
                asm volatile("cp.async.cg.shared.global [%0], [%1], 16;" :: "r"(dst), "l"(s));
            }
        }
        {
            #pragma unroll
            for (int u = 0; u < 8; u++) {
                int gi = tid + u*256;
                int r = gi >> 4, c4 = gi & 15;
                int v = v0 + r;
                uint32_t dst = smb + buf*L_STG + L_ASTG + (uint32_t)(r*L_BLD + c4*4)*4;
                const float* s = (v < N) ? (W + (size_t)v*HID + kc*64 + c4*4) : W;
                unsigned sz = (v < N) ? 16u : 0u;
                asm volatile("cp.async.cg.shared.global [%0], [%1], 16, %2;"
                             :: "r"(dst), "l"(s), "r"(sz));
            }
        }
        asm volatile("cp.async.commit_group;" ::: "memory");
    };

    issue(0); issue(1);

    #pragma unroll
    for (int mt = 0; mt < 2; mt++)
        #pragma unroll
        for (int nt = 0; nt < 4; nt++)
            #pragma unroll
            for (int i = 0; i < 4; i++) acc[mt][nt][i] = 0.f;

    for (int kc = 0; kc < 16; kc++) {
        const int buf = kc % 3;
        asm volatile("cp.async.wait_group 1;" ::: "memory");
        __syncthreads();

        const float* A_s = (const float*)(sm + buf*L_STG);
        const float* B_s = (const float*)(sm + buf*L_STG + L_ASTG);
        #pragma unroll
        for (int kk = 0; kk < 8; kk++) {
            const int ka = kk*8 + qt;
            unsigned a[2][4];
            #pragma unroll
            for (int mt = 0; mt < 2; mt++) {
                int r = wm*32 + mt*16 + g;
                a[mt][0] = __float_as_uint(to_tf32(A_s[r*L_ALD + ka]));
                a[mt][1] = __float_as_uint(to_tf32(A_s[(r+8)*L_ALD + ka]));
                a[mt][2] = __float_as_uint(to_tf32(A_s[r*L_ALD + ka + 4]));
                a[mt][3] = __float_as_uint(to_tf32(A_s[(r+8)*L_ALD + ka + 4]));
            }
            #pragma unroll
            for (int nt = 0; nt < 4; nt++) {
                int cn = wn*32 + nt*8 + g;
                unsigned b0 = __float_as_uint(to_tf32(B_s[cn*L_BLD + ka]));
                unsigned b1 = __float_as_uint(to_tf32(B_s[cn*L_BLD + ka + 4]));
                #pragma unroll
                for (int mt = 0; mt < 2; mt++) {
                    asm volatile(
                        "mma.sync.aligned.m16n8k8.row.col.f32.tf32.tf32.f32 "
                        "{%0,%1,%2,%3}, {%4,%5,%6,%7}, {%8,%9}, {%0,%1,%2,%3};"
                        : "+f"(acc[mt][nt][0]), "+f"(acc[mt][nt][1]),
                          "+f"(acc[mt][nt][2]), "+f"(acc[mt][nt][3])
                        : "r"(a[mt][0]), "r"(a[mt][1]), "r"(a[mt][2]), "r"(a[mt][3]),
                          "r"(b0), "r"(b1));
                }
            }
        }
        if (kc + 2 < 16) issue(kc + 2);
    }
}

// gi/gh GEMM combined: blockIdx.y selects (1: gh from hidden/W_hh, 0: gi).
__global__ void __launch_bounds__(256) k_gru_tc(const float* __restrict__ hidden,
                                                const float* __restrict__ W_ih,
                                                const float* __restrict__ W_hh) {
    extern __shared__ char sm[];
    const uint32_t smb = smem_u32(sm);
    const int which = blockIdx.y;
    const float* Amat = which ? hidden : g_x;
    const float* W    = which ? W_hh   : W_ih;
    float*       C    = which ? g_gh   : g_gi;
    const int v0 = blockIdx.x * 128;

    float acc[2][4][4];
    gemm_tc_body(Amat, W, v0, 3*HID, smb, sm, acc);

    const int lane = threadIdx.x & 31;
    const int warp = threadIdx.x >> 5;
    const int wm = warp >> 2, wn = warp & 3;
    const int g = lane >> 2, qt = lane & 3;
    #pragma unroll
    for (int mt = 0; mt < 2; mt++) {
        int r0 = wm*32 + mt*16 + g;
        #pragma unroll
        for (int nt = 0; nt < 4; nt++) {
            int c0 = v0 + wn*32 + nt*8 + qt*2;
            C[(size_t)r0*3*HID + c0]         = acc[mt][nt][0];
            C[(size_t)r0*3*HID + c0 + 1]     = acc[mt][nt][1];
            C[(size_t)(r0+8)*3*HID + c0]     = acc[mt][nt][2];
            C[(size_t)(r0+8)*3*HID + c0 + 1] = acc[mt][nt][3];
        }
    }
}

// logits GEMM (bias added)
__global__ void __launch_bounds__(256) k_logits_tc8(const float* __restrict__ W_out,
                                                    const float* __restrict__ b_out,
                                                    float* __restrict__ logits) {
    extern __shared__ char sm[];
    const uint32_t smb = smem_u32(sm);
    const int v0 = blockIdx.x * 128;

    float acc[2][4][4];
    gemm_tc_body(g_h, W_out, v0, VOCAB, smb, sm, acc);

    const int lane = threadIdx.x & 31;
    const int warp = threadIdx.x >> 5;
    const int wm = warp >> 2, wn = warp & 3;
    const int g = lane >> 2, qt = lane & 3;
    #pragma unroll
    for (int mt = 0; mt < 2; mt++) {
        int r0 = wm*32 + mt*16 + g;
        #pragma unroll
        for (int nt = 0; nt < 4; nt++) {
            int c0 = v0 + wn*32 + nt*8 + qt*2;
            if (c0 + 1 < VOCAB) {
                float bo0 = b_out[c0], bo1 = b_out[c0+1];
                logits[(size_t)r0*VOCAB + c0]         = acc[mt][nt][0] + bo0;
                logits[(size_t)r0*VOCAB + c0 + 1]     = acc[mt][nt][1] + bo1;
                logits[(size_t)(r0+8)*VOCAB + c0]     = acc[mt][nt][2] + bo0;
                logits[(size_t)(r0+8)*VOCAB + c0 + 1] = acc[mt][nt][3] + bo1;
            } else if (c0 < VOCAB) {
                float bo0 = b_out[c0];
                logits[(size_t)r0*VOCAB + c0]     = acc[mt][nt][0] + bo0;
                logits[(size_t)(r0+8)*VOCAB + c0] = acc[mt][nt][2] + bo0;
            }
        }
    }
}

// ---------------- GRU gates ------------------------------------------------
__global__ void __launch_bounds__(256) k_gates(const float* __restrict__ hidden,
                                               const float* __restrict__ b_ih,
                                               const float* __restrict__ b_hh,
                                               float* __restrict__ o_out) {
    int j = blockIdx.x * 256 + threadIdx.x;
    int b = blockIdx.y;
    float ir  = g_gi[b*3*HID + j]         + b_ih[j];
    float iz  = g_gi[b*3*HID + HID + j]   + b_ih[HID + j];
    float inn = g_gi[b*3*HID + 2*HID + j] + b_ih[2*HID + j];
    float hr  = g_gh[b*3*HID + j]         + b_hh[j];
    float hz  = g_gh[b*3*HID + HID + j]   + b_hh[HID + j];
    float hn  = g_gh[b*3*HID + 2*HID + j] + b_hh[2*HID + j];
    float r = 1.f / (1.f + expf(-(ir + hr)));
    float z = 1.f / (1.f + expf(-(iz + hz)));
    float n = tanhf(inn + r * hn);
    float q = hidden[b*HID + j];
    float h = (1.f - z) * n + z * q;
    g_h[b*HID + j]   = h;
    o_out[b*HID + j] = h;
}

// ---------------- split logsumexp ------------------------------------------
#define LSE_CH 6283            // ceil(VOCAB/8)
__global__ void __launch_bounds__(256) k_lse1(const float* __restrict__ logits) {
    int b = blockIdx.x, p = blockIdx.y, tid = threadIdx.x;
    __shared__ float red[256];
    const float* row = logits + (size_t)b*VOCAB;
    int start = p*LSE_CH;
    int end = start + LSE_CH; if (end > VOCAB) end = VOCAB;
    float m = -1e30f;
    for (int v = start + tid; v < end; v += 256) m = fmaxf(m, row[v]);
    red[tid] = m; __syncthreads();
    for (int s = 128; s; s >>= 1) { if (tid < s) red[tid] = fmaxf(red[tid], red[tid+s]); __syncthreads(); }
    m = red[0]; __syncthreads();
    float sum = 0.f;
    for (int v = start + tid; v < end; v += 256) sum += expf(row[v] - m);
    red[tid] = sum; __syncthreads();
    for (int s = 128; s; s >>= 1) { if (tid < s) red[tid] += red[tid+s]; __syncthreads(); }
    if (tid == 0) { g_pm[b*8 + p] = m; g_ps[b*8 + p] = red[0]; }
}

__global__ void __launch_bounds__(64) k_lse2() {
    int b = threadIdx.x;
    float m = -1e30f;
    #pragma unroll
    for (int p = 0; p < 8; p++) m = fmaxf(m, g_pm[b*8 + p]);
    float s = 0.f;
    #pragma unroll
    for (int p = 0; p < 8; p++) s += g_ps[b*8 + p] * expf(g_pm[b*8 + p] - m);
    g_lse[b] = m + logf(s);
}

__global__ void __launch_bounds__(256) k_sub(float* __restrict__ logp) {
    int v = blockIdx.x * 256 + threadIdx.x;
    int b = blockIdx.y;
    if (v < VOCAB) logp[(size_t)b*VOCAB + v] -= g_lse[b];
}

// ---------------- launcher -------------------------------------------------
extern "C" void kernel_launch(void* const* d_in, const int* in_sizes, int n_in,
                              void* d_out, int out_size) {
    const int*   ids    = (const int*)d_in[0];
    const float* hidden = (const float*)d_in[1];
    const float* ann    = (const float*)d_in[2];
    const float* emb    = (const float*)d_in[3];
    const float* Wk     = (const float*)d_in[4];
    const float* Wq     = (const float*)d_in[5];
    const float* bk     = (const float*)d_in[6];
    const float* v_attn = (const float*)d_in[7];
    const float* W_ih   = (const float*)d_in[8];
    const float* W_hh   = (const float*)d_in[9];
    const float* b_ih   = (const float*)d_in[10];
    const float* b_hh   = (const float*)d_in[11];
    const float* W_out  = (const float*)d_in[12];
    const float* b_out  = (const float*)d_in[13];

    float* out   = (float*)d_out;
    float* logp  = out;
    float* o_out = out + O_OFF;
    float* a_out = out + A_OFF;

    cudaFuncSetAttribute(k_feat8,      cudaFuncAttributeMaxDynamicSharedMemorySize, FEAT_SMEM);
    cudaFuncSetAttribute(k_gru_tc,     cudaFuncAttributeMaxDynamicSharedMemorySize, LOG_SMEM);
    cudaFuncSetAttribute(k_logits_tc8, cudaFuncAttributeMaxDynamicSharedMemorySize, LOG_SMEM);

    k_wkr       <<<(KEY*HID)/256, 256>>>(Wk);
    k_qw        <<<dim3(HID/256, B), 256>>>(hidden, Wq, bk);
    k_feat8     <<<(B*NK)/64, 1024, FEAT_SMEM>>>(ann, v_attn);
    k_attn_sm   <<<B, 256>>>(ids, emb, a_out);
    k_ctx       <<<dim3(B, 8), 256>>>(ann, a_out);
    k_gru_tc    <<<dim3(3*HID/128, 2), 256, LOG_SMEM>>>(hidden, W_ih, W_hh);
    k_gates     <<<dim3(HID/256, B), 256>>>(hidden, b_ih, b_hh, o_out);
    k_logits_tc8<<<(VOCAB + 127)/128, 256, LOG_SMEM>>>(W_out, b_out, logp);
    k_lse1      <<<dim3(B, 8), 256>>>(logp);
    k_lse2      <<<1, 64>>>();
    k_sub       <<<dim3((VOCAB + 255)/256, B), 256>>>(logp);
}

// round 10
// speedup vs baseline: 1.0830x; 1.0830x over previous
#include <cuda_runtime.h>
#include <math.h>
#include <stdint.h>

#define B 64
#define NK 2048
#define HID 1024
#define EMB 512
#define KEY 512
#define VOCAB 50257

#define O_OFF (B*VOCAB)
#define A_OFF (O_OFF + B*HID)

// ---------------- scratch ---------------------------------------------------
__device__ float g_qw[B*HID];
__device__ float g_scores[B*NK];
__device__ float g_x[B*(EMB+KEY)];
__device__ float g_h[B*HID];
__device__ float g_gi[B*3*HID];
__device__ float g_gh[B*3*HID];
__device__ float g_lse[B];
__device__ float g_pm[B*8];
__device__ float g_ps[B*8];
__device__ float g_wkR[KEY*HID];      // Wk tf32-rounded (RNA), [k][n]

__device__ __forceinline__ float to_tf32(float x) {
    unsigned r;
    asm("cvt.rna.tf32.f32 %0, %1;" : "=r"(r) : "f"(x));
    return __uint_as_float(r);
}
__device__ __forceinline__ uint32_t smem_u32(const void* p) {
    uint32_t a;
    asm("{ .reg .u64 t; cvta.to.shared.u64 t, %1; cvt.u32.u64 %0, t; }" : "=r"(a) : "l"(p));
    return a;
}

// ---------------- kernel: round Wk to tf32 ---------------------------------
__global__ void __launch_bounds__(256) k_wkr(const float* __restrict__ Wk) {
    int i = blockIdx.x * 256 + threadIdx.x;
    g_wkR[i] = to_tf32(Wk[i]);
}

// ---------------- kernel: qw = Q @ Wq + bk ---------------------------------
__global__ void __launch_bounds__(256) k_qw(const float* __restrict__ hidden,
                                            const float* __restrict__ Wq,
                                            const float* __restrict__ bk) {
    int h = blockIdx.x * 256 + threadIdx.x;
    int b = blockIdx.y;
    __shared__ float q_s[HID];
    for (int i = threadIdx.x; i < HID; i += 256) q_s[i] = hidden[b*HID + i];
    __syncthreads();
    float acc = bk[h];
    #pragma unroll 8
    for (int k = 0; k < HID; k++)
        acc = fmaf(q_s[k], Wq[(size_t)k*HID + h], acc);
    g_qw[b*HID + h] = acc;
}

// ---------------- feat GEMM: tf32 mma, 512 thr, fragment-major A -----------
// (round-8 proven config: best feat measured, 16 warps, wm(2) x wn(8), nt=4)
#define BLD 264
#define B_STG (16*BLD*4)                 // 16896 bytes
#define F_A   0
#define F_B   (64*512*4)                 // 131072
#define F_QW  (F_B + 4*B_STG)            // 198656
#define F_V   (F_QW + HID*4)
#define F_SC  (F_V + HID*4)
#define FEAT_SMEM (F_SC + 64*4)          // 207104

__global__ void __launch_bounds__(512) k_feat7(const float* __restrict__ ann,
                                               const float* __restrict__ v_attn) {
    extern __shared__ char sm[];
    const uint32_t smb = smem_u32(sm);
    float* A_f  = (float*)(sm + F_A);
    float* qw_s = (float*)(sm + F_QW);
    float* v_s  = (float*)(sm + F_V);
    float* sc_s = (float*)(sm + F_SC);

    const int bx   = blockIdx.x;
    const int b    = bx >> 5;
    const int row0 = (bx & 31) * 64;
    const int tid  = threadIdx.x;
    const int lane = tid & 31;
    const int warp = tid >> 5;
    const int wm   = warp >> 3;       // 0..1
    const int wn   = warp & 7;        // 0..7
    const int g    = lane >> 2;       // 0..7
    const int qt   = lane & 3;        // 0..3

    for (int i = tid; i < HID; i += 512) {
        qw_s[i] = g_qw[b*HID + i];
        v_s[i]  = v_attn[i];
    }
    if (tid < 64) sc_s[tid] = 0.f;

    // A tile -> fragment-major layout, tf32-rounded (RNA). One-time.
    {
        const float4* src = (const float4*)(ann + ((size_t)b * NK + row0) * KEY);
        for (int i = tid; i < 64*128; i += 512) {
            int r  = i >> 7;
            int k4 = i & 127;
            float4 v4 = src[i];
            v4.x = to_tf32(v4.x); v4.y = to_tf32(v4.y);
            v4.z = to_tf32(v4.z); v4.w = to_tf32(v4.w);
            int ko   = k4 >> 1;
            int half = k4 & 1;
            int rg   = r >> 4;
            int hi8  = (r >> 3) & 1;
            int gg   = r & 7;
            int slot = (half << 1) | hi8;
            float* base = A_f + (ko*4 + rg)*128;
            base[(gg*4 + 0)*4 + slot] = v4.x;
            base[(gg*4 + 1)*4 + slot] = v4.y;
            base[(gg*4 + 2)*4 + slot] = v4.z;
            base[(gg*4 + 3)*4 + slot] = v4.w;
        }
    }

    // stage: 16 k-rows x 256 n-cols of Wk
    auto issue = [&](int it) {
        int ncc = it >> 5, kc = it & 31, buf = it & 3;
        const float* src = g_wkR + (size_t)(kc*16)*HID + ncc*256;
        #pragma unroll
        for (int u = 0; u < 2; u++) {
            int gi = tid + u*512;
            int r = gi >> 6, c4 = gi & 63;
            uint32_t dst = smb + F_B + buf*B_STG + (uint32_t)(r*BLD + c4*4)*4;
            const float* s = src + (size_t)r*HID + c4*4;
            asm volatile("cp.async.cg.shared.global [%0], [%1], 16;" :: "r"(dst), "l"(s));
        }
        asm volatile("cp.async.commit_group;" ::: "memory");
    };

    issue(0); issue(1); issue(2);

    float rs[2][2] = {{0.f,0.f},{0.f,0.f}};
    float acc[2][4][4];
    const int rgbase = wm*2;

    for (int it = 0; it < 128; it++) {
        const int buf = it & 3;
        const int kc  = it & 31;
        asm volatile("cp.async.wait_group 2;" ::: "memory");
        __syncthreads();

        if (kc == 0) {
            #pragma unroll
            for (int mt = 0; mt < 2; mt++)
                #pragma unroll
                for (int nt = 0; nt < 4; nt++)
                    #pragma unroll
                    for (int i = 0; i < 4; i++) acc[mt][nt][i] = 0.f;
        }

        const float* Bst = (const float*)(sm + F_B + buf*B_STG);

        float4 af[2][2];
        unsigned bf[2][4][2];
        #pragma unroll
        for (int kk = 0; kk < 2; kk++) {
            const int ko = kc*2 + kk;
            #pragma unroll
            for (int mt = 0; mt < 2; mt++)
                af[kk][mt] = *(const float4*)(A_f + ((ko*4 + rgbase + mt)*32 + lane)*4);
            #pragma unroll
            for (int nt = 0; nt < 4; nt++) {
                int cn = wn*32 + nt*8 + g;
                bf[kk][nt][0] = __float_as_uint(Bst[(kk*8 + qt)*BLD + cn]);
                bf[kk][nt][1] = __float_as_uint(Bst[(kk*8 + qt + 4)*BLD + cn]);
            }
        }
        #pragma unroll
        for (int kk = 0; kk < 2; kk++) {
            #pragma unroll
            for (int nt = 0; nt < 4; nt++) {
                #pragma unroll
                for (int mt = 0; mt < 2; mt++) {
                    asm volatile(
                        "mma.sync.aligned.m16n8k8.row.col.f32.tf32.tf32.f32 "
                        "{%0,%1,%2,%3}, {%4,%5,%6,%7}, {%8,%9}, {%0,%1,%2,%3};"
                        : "+f"(acc[mt][nt][0]), "+f"(acc[mt][nt][1]),
                          "+f"(acc[mt][nt][2]), "+f"(acc[mt][nt][3])
                        : "r"(__float_as_uint(af[kk][mt].x)),
                          "r"(__float_as_uint(af[kk][mt].y)),
                          "r"(__float_as_uint(af[kk][mt].z)),
                          "r"(__float_as_uint(af[kk][mt].w)),
                          "r"(bf[kk][nt][0]), "r"(bf[kk][nt][1]));
                }
            }
        }

        if (kc == 31) {
            const int ncc = it >> 5;
            #pragma unroll
            for (int mt = 0; mt < 2; mt++)
                #pragma unroll
                for (int nt = 0; nt < 4; nt++) {
                    int h0 = ncc*256 + wn*32 + nt*8 + qt*2;
                    float v0 = v_s[h0],     q0u = qw_s[h0];
                    float v1 = v_s[h0 + 1], q1u = qw_s[h0 + 1];
                    rs[mt][0] = fmaf(v0, tanhf(acc[mt][nt][0] + q0u), rs[mt][0]);
                    rs[mt][0] = fmaf(v1, tanhf(acc[mt][nt][1] + q1u), rs[mt][0]);
                    rs[mt][1] = fmaf(v0, tanhf(acc[mt][nt][2] + q0u), rs[mt][1]);
                    rs[mt][1] = fmaf(v1, tanhf(acc[mt][nt][3] + q1u), rs[mt][1]);
                }
        }

        if (it + 3 < 128) issue(it + 3);
    }

    #pragma unroll
    for (int mt = 0; mt < 2; mt++)
        #pragma unroll
        for (int up = 0; up < 2; up++) {
            float p = rs[mt][up];
            p += __shfl_xor_sync(0xffffffffu, p, 1);
            p += __shfl_xor_sync(0xffffffffu, p, 2);
            if (qt == 0)
                atomicAdd(&sc_s[wm*32 + mt*16 + up*8 + g], p);
        }
    __syncthreads();
    if (tid < 64) g_scores[(size_t)b*NK + row0 + tid] = sc_s[tid];
}

// ---------------- softmax + emb copy ---------------------------------------
__global__ void __launch_bounds__(256) k_attn_sm(const int* __restrict__ ids,
                                                 const float* __restrict__ emb_table,
                                                 float* __restrict__ a_out) {
    int b = blockIdx.x;
    int tid = threadIdx.x;
    __shared__ float sc[NK];
    __shared__ float red[256];

    float m = -1e30f;
    for (int i = tid; i < NK; i += 256) {
        float v = g_scores[b*NK + i];
        sc[i] = v;
        m = fmaxf(m, v);
    }
    red[tid] = m; __syncthreads();
    for (int s = 128; s; s >>= 1) { if (tid < s) red[tid] = fmaxf(red[tid], red[tid+s]); __syncthreads(); }
    m = red[0]; __syncthreads();

    float sum = 0.f;
    for (int i = tid; i < NK; i += 256) { float e = expf(sc[i] - m); sc[i] = e; sum += e; }
    red[tid] = sum; __syncthreads();
    for (int s = 128; s; s >>= 1) { if (tid < s) red[tid] += red[tid+s]; __syncthreads(); }
    float inv = 1.f / red[0];
    __syncthreads();

    for (int i = tid; i < NK; i += 256)
        a_out[(size_t)b*NK + i] = sc[i] * inv;

    int id = ids[b];
    for (int k = tid; k < EMB; k += 256)
        g_x[b*(EMB+KEY) + k] = emb_table[(size_t)id*EMB + k];
}

// ---------------- context = a . ann ----------------------------------------
// grid (B, 16): 32-col slice per block, 8 row-groups x 32 cols.
__global__ void __launch_bounds__(256) k_ctx(const float* __restrict__ ann,
                                             const float* __restrict__ a_out) {
    int b = blockIdx.x;
    int p = blockIdx.y;
    int tid = threadIdx.x;
    int c  = tid & 31;
    int rg = tid >> 5;
    __shared__ float part[8][33];

    const float* ab = ann + (size_t)b*NK*KEY + p*32 + c;
    const float* av = a_out + (size_t)b*NK;
    float acc = 0.f;
    for (int n = rg; n < NK; n += 8)
        acc = fmaf(av[n], ab[(size_t)n*KEY], acc);
    part[rg][c] = acc;
    __syncthreads();
    if (rg == 0) {
        float s = part[0][c] + part[1][c] + part[2][c] + part[3][c]
                + part[4][c] + part[5][c] + part[6][c] + part[7][c];
        g_x[b*(EMB+KEY) + EMB + p*32 + c] = s;
    }
}

// ---------------- shared tf32 GEMM body (RNA-rounded fragments) ------------
#define L_ALD 68
#define L_BLD 68
#define L_ASTG (64*L_ALD*4)
#define L_BSTG (128*L_BLD*4)
#define L_STG  (L_ASTG + L_BSTG)
#define LOG_SMEM (3*L_STG)               // 156672

__device__ __forceinline__ void gemm_tc_body(const float* __restrict__ Amat,
                                             const float* __restrict__ W,
                                             int v0, int N, uint32_t smb, char* sm,
                                             float acc[2][4][4]) {
    const int tid = threadIdx.x;
    const int lane = tid & 31;
    const int warp = tid >> 5;
    const int wm = warp >> 2;
    const int wn = warp & 3;
    const int g  = lane >> 2;
    const int qt = lane & 3;

    auto issue = [&](int kc) {
        int buf = kc % 3;
        {
            const float* src = Amat + kc*64;
            #pragma unroll
            for (int u = 0; u < 4; u++) {
                int gi = tid + u*256;
                int r = gi >> 4, c4 = gi & 15;
                uint32_t dst = smb + buf*L_STG + (uint32_t)(r*L_ALD + c4*4)*4;
                const float* s = src + (size_t)r*HID + c4*4;
                asm volatile("cp.async.cg.shared.global [%0], [%1], 16;" :: "r"(dst), "l"(s));
            }
        }
        {
            #pragma unroll
            for (int u = 0; u < 8; u++) {
                int gi = tid + u*256;
                int r = gi >> 4, c4 = gi & 15;
                int v = v0 + r;
                uint32_t dst = smb + buf*L_STG + L_ASTG + (uint32_t)(r*L_BLD + c4*4)*4;
                const float* s = (v < N) ? (W + (size_t)v*HID + kc*64 + c4*4) : W;
                unsigned sz = (v < N) ? 16u : 0u;
                asm volatile("cp.async.cg.shared.global [%0], [%1], 16, %2;"
                             :: "r"(dst), "l"(s), "r"(sz));
            }
        }
        asm volatile("cp.async.commit_group;" ::: "memory");
    };

    issue(0); issue(1);

    #pragma unroll
    for (int mt = 0; mt < 2; mt++)
        #pragma unroll
        for (int nt = 0; nt < 4; nt++)
            #pragma unroll
            for (int i = 0; i < 4; i++) acc[mt][nt][i] = 0.f;

    for (int kc = 0; kc < 16; kc++) {
        const int buf = kc % 3;
        asm volatile("cp.async.wait_group 1;" ::: "memory");
        __syncthreads();

        const float* A_s = (const float*)(sm + buf*L_STG);
        const float* B_s = (const float*)(sm + buf*L_STG + L_ASTG);
        #pragma unroll
        for (int kk = 0; kk < 8; kk++) {
            const int ka = kk*8 + qt;
            unsigned a[2][4];
            #pragma unroll
            for (int mt = 0; mt < 2; mt++) {
                int r = wm*32 + mt*16 + g;
                a[mt][0] = __float_as_uint(to_tf32(A_s[r*L_ALD + ka]));
                a[mt][1] = __float_as_uint(to_tf32(A_s[(r+8)*L_ALD + ka]));
                a[mt][2] = __float_as_uint(to_tf32(A_s[r*L_ALD + ka + 4]));
                a[mt][3] = __float_as_uint(to_tf32(A_s[(r+8)*L_ALD + ka + 4]));
            }
            #pragma unroll
            for (int nt = 0; nt < 4; nt++) {
                int cn = wn*32 + nt*8 + g;
                unsigned b0 = __float_as_uint(to_tf32(B_s[cn*L_BLD + ka]));
                unsigned b1 = __float_as_uint(to_tf32(B_s[cn*L_BLD + ka + 4]));
                #pragma unroll
                for (int mt = 0; mt < 2; mt++) {
                    asm volatile(
                        "mma.sync.aligned.m16n8k8.row.col.f32.tf32.tf32.f32 "
                        "{%0,%1,%2,%3}, {%4,%5,%6,%7}, {%8,%9}, {%0,%1,%2,%3};"
                        : "+f"(acc[mt][nt][0]), "+f"(acc[mt][nt][1]),
                          "+f"(acc[mt][nt][2]), "+f"(acc[mt][nt][3])
                        : "r"(a[mt][0]), "r"(a[mt][1]), "r"(a[mt][2]), "r"(a[mt][3]),
                          "r"(b0), "r"(b1));
                }
            }
        }
        if (kc + 2 < 16) issue(kc + 2);
    }
}

// gi/gh GEMM combined: blockIdx.y selects (1: gh from hidden/W_hh, 0: gi).
__global__ void __launch_bounds__(256) k_gru_tc(const float* __restrict__ hidden,
                                                const float* __restrict__ W_ih,
                                                const float* __restrict__ W_hh) {
    extern __shared__ char sm[];
    const uint32_t smb = smem_u32(sm);
    const int which = blockIdx.y;
    const float* Amat = which ? hidden : g_x;
    const float* W    = which ? W_hh   : W_ih;
    float*       C    = which ? g_gh   : g_gi;
    const int v0 = blockIdx.x * 128;

    float acc[2][4][4];
    gemm_tc_body(Amat, W, v0, 3*HID, smb, sm, acc);

    const int lane = threadIdx.x & 31;
    const int warp = threadIdx.x >> 5;
    const int wm = warp >> 2, wn = warp & 3;
    const int g = lane >> 2, qt = lane & 3;
    #pragma unroll
    for (int mt = 0; mt < 2; mt++) {
        int r0 = wm*32 + mt*16 + g;
        #pragma unroll
        for (int nt = 0; nt < 4; nt++) {
            int c0 = v0 + wn*32 + nt*8 + qt*2;
            C[(size_t)r0*3*HID + c0]         = acc[mt][nt][0];
            C[(size_t)r0*3*HID + c0 + 1]     = acc[mt][nt][1];
            C[(size_t)(r0+8)*3*HID + c0]     = acc[mt][nt][2];
            C[(size_t)(r0+8)*3*HID + c0 + 1] = acc[mt][nt][3];
        }
    }
}

// logits GEMM (bias added)
__global__ void __launch_bounds__(256) k_logits_tc9(const float* __restrict__ W_out,
                                                    const float* __restrict__ b_out,
                                                    float* __restrict__ logits) {
    extern __shared__ char sm[];
    const uint32_t smb = smem_u32(sm);
    const int v0 = blockIdx.x * 128;

    float acc[2][4][4];
    gemm_tc_body(g_h, W_out, v0, VOCAB, smb, sm, acc);

    const int lane = threadIdx.x & 31;
    const int warp = threadIdx.x >> 5;
    const int wm = warp >> 2, wn = warp & 3;
    const int g = lane >> 2, qt = lane & 3;
    #pragma unroll
    for (int mt = 0; mt < 2; mt++) {
        int r0 = wm*32 + mt*16 + g;
        #pragma unroll
        for (int nt = 0; nt < 4; nt++) {
            int c0 = v0 + wn*32 + nt*8 + qt*2;
            if (c0 + 1 < VOCAB) {
                float bo0 = b_out[c0], bo1 = b_out[c0+1];
                logits[(size_t)r0*VOCAB + c0]         = acc[mt][nt][0] + bo0;
                logits[(size_t)r0*VOCAB + c0 + 1]     = acc[mt][nt][1] + bo1;
                logits[(size_t)(r0+8)*VOCAB + c0]     = acc[mt][nt][2] + bo0;
                logits[(size_t)(r0+8)*VOCAB + c0 + 1] = acc[mt][nt][3] + bo1;
            } else if (c0 < VOCAB) {
                float bo0 = b_out[c0];
                logits[(size_t)r0*VOCAB + c0]     = acc[mt][nt][0] + bo0;
                logits[(size_t)(r0+8)*VOCAB + c0] = acc[mt][nt][2] + bo0;
            }
        }
    }
}

// ---------------- GRU gates ------------------------------------------------
__global__ void __launch_bounds__(256) k_gates(const float* __restrict__ hidden,
                                               const float* __restrict__ b_ih,
                                               const float* __restrict__ b_hh,
                                               float* __restrict__ o_out) {
    int j = blockIdx.x * 256 + threadIdx.x;
    int b = blockIdx.y;
    float ir  = g_gi[b*3*HID + j]         + b_ih[j];
    float iz  = g_gi[b*3*HID + HID + j]   + b_ih[HID + j];
    float inn = g_gi[b*3*HID + 2*HID + j] + b_ih[2*HID + j];
    float hr  = g_gh[b*3*HID + j]         + b_hh[j];
    float hz  = g_gh[b*3*HID + HID + j]   + b_hh[HID + j];
    float hn  = g_gh[b*3*HID + 2*HID + j] + b_hh[2*HID + j];
    float r = 1.f / (1.f + expf(-(ir + hr)));
    float z = 1.f / (1.f + expf(-(iz + hz)));
    float n = tanhf(inn + r * hn);
    float q = hidden[b*HID + j];
    float h = (1.f - z) * n + z * q;
    g_h[b*HID + j]   = h;
    o_out[b*HID + j] = h;
}

// ---------------- split logsumexp ------------------------------------------
#define LSE_CH 6283            // ceil(VOCAB/8)
__global__ void __launch_bounds__(256) k_lse1(const float* __restrict__ logits) {
    int b = blockIdx.x, p = blockIdx.y, tid = threadIdx.x;
    __shared__ float red[256];
    const float* row = logits + (size_t)b*VOCAB;
    int start = p*LSE_CH;
    int end = start + LSE_CH; if (end > VOCAB) end = VOCAB;
    float m = -1e30f;
    for (int v = start + tid; v < end; v += 256) m = fmaxf(m, row[v]);
    red[tid] = m; __syncthreads();
    for (int s = 128; s; s >>= 1) { if (tid < s) red[tid] = fmaxf(red[tid], red[tid+s]); __syncthreads(); }
    m = red[0]; __syncthreads();
    float sum = 0.f;
    for (int v = start + tid; v < end; v += 256) sum += expf(row[v] - m);
    red[tid] = sum; __syncthreads();
    for (int s = 128; s; s >>= 1) { if (tid < s) red[tid] += red[tid+s]; __syncthreads(); }
    if (tid == 0) { g_pm[b*8 + p] = m; g_ps[b*8 + p] = red[0]; }
}

__global__ void __launch_bounds__(64) k_lse2() {
    int b = threadIdx.x;
    float m = -1e30f;
    #pragma unroll
    for (int p = 0; p < 8; p++) m = fmaxf(m, g_pm[b*8 + p]);
    float s = 0.f;
    #pragma unroll
    for (int p = 0; p < 8; p++) s += g_ps[b*8 + p] * expf(g_pm[b*8 + p] - m);
    g_lse[b] = m + logf(s);
}

__global__ void __launch_bounds__(256) k_sub(float* __restrict__ logp) {
    int v = blockIdx.x * 256 + threadIdx.x;
    int b = blockIdx.y;
    if (v < VOCAB) logp[(size_t)b*VOCAB + v] -= g_lse[b];
}

// ---------------- launcher -------------------------------------------------
extern "C" void kernel_launch(void* const* d_in, const int* in_sizes, int n_in,
                              void* d_out, int out_size) {
    const int*   ids    = (const int*)d_in[0];
    const float* hidden = (const float*)d_in[1];
    const float* ann    = (const float*)d_in[2];
    const float* emb    = (const float*)d_in[3];
    const float* Wk     = (const float*)d_in[4];
    const float* Wq     = (const float*)d_in[5];
    const float* bk     = (const float*)d_in[6];
    const float* v_attn = (const float*)d_in[7];
    const float* W_ih   = (const float*)d_in[8];
    const float* W_hh   = (const float*)d_in[9];
    const float* b_ih   = (const float*)d_in[10];
    const float* b_hh   = (const float*)d_in[11];
    const float* W_out  = (const float*)d_in[12];
    const float* b_out  = (const float*)d_in[13];

    float* out   = (float*)d_out;
    float* logp  = out;
    float* o_out = out + O_OFF;
    float* a_out = out + A_OFF;

    cudaFuncSetAttribute(k_feat7,      cudaFuncAttributeMaxDynamicSharedMemorySize, FEAT_SMEM);
    cudaFuncSetAttribute(k_gru_tc,     cudaFuncAttributeMaxDynamicSharedMemorySize, LOG_SMEM);
    cudaFuncSetAttribute(k_logits_tc9, cudaFuncAttributeMaxDynamicSharedMemorySize, LOG_SMEM);

    k_wkr       <<<(KEY*HID)/256, 256>>>(Wk);
    k_qw        <<<dim3(HID/256, B), 256>>>(hidden, Wq, bk);
    k_feat7     <<<(B*NK)/64, 512, FEAT_SMEM>>>(ann, v_attn);
    k_attn_sm   <<<B, 256>>>(ids, emb, a_out);
    k_ctx       <<<dim3(B, 16), 256>>>(ann, a_out);
    k_gru_tc    <<<dim3(3*HID/128, 2), 256, LOG_SMEM>>>(hidden, W_ih, W_hh);
    k_gates     <<<dim3(HID/256, B), 256>>>(hidden, b_ih, b_hh, o_out);
    k_logits_tc9<<<(VOCAB + 127)/128, 256, LOG_SMEM>>>(W_out, b_out, logp);
    k_lse1      <<<dim3(B, 8), 256>>>(logp);
    k_lse2      <<<1, 64>>>();
    k_sub       <<<dim3((VOCAB + 255)/256, B), 256>>>(logp);
}

// round 11
// speedup vs baseline: 1.1770x; 1.0868x over previous
#include <cuda_runtime.h>
#include <math.h>
#include <stdint.h>

#define B 64
#define NK 2048
#define HID 1024
#define EMB 512
#define KEY 512
#define VOCAB 50257

#define O_OFF (B*VOCAB)
#define A_OFF (O_OFF + B*HID)

// ---------------- scratch ---------------------------------------------------
__device__ float g_qw[B*HID];
__device__ float g_scores[B*NK];
__device__ float g_x[B*(EMB+KEY)];
__device__ float g_h[B*HID];
__device__ float g_gi[B*3*HID];
__device__ float g_gh[B*3*HID];
__device__ float g_lse[B];
__device__ float g_pm[B*8];
__device__ float g_ps[B*8];
__device__ float g_wkR[KEY*HID];      // Wk tf32-rounded (RNA), [k][n]

__device__ __forceinline__ float to_tf32(float x) {
    unsigned r;
    asm("cvt.rna.tf32.f32 %0, %1;" : "=r"(r) : "f"(x));
    return __uint_as_float(r);
}
__device__ __forceinline__ uint32_t smem_u32(const void* p) {
    uint32_t a;
    asm("{ .reg .u64 t; cvta.to.shared.u64 t, %1; cvt.u32.u64 %0, t; }" : "=r"(a) : "l"(p));
    return a;
}

// ---------------- kernel: round Wk to tf32 ---------------------------------
__global__ void __launch_bounds__(256) k_wkr(const float* __restrict__ Wk) {
    int i = blockIdx.x * 256 + threadIdx.x;
    g_wkR[i] = to_tf32(Wk[i]);
}

// ---------------- kernel: qw = Q @ Wq + bk ---------------------------------
__global__ void __launch_bounds__(256) k_qw(const float* __restrict__ hidden,
                                            const float* __restrict__ Wq,
                                            const float* __restrict__ bk) {
    int h = blockIdx.x * 256 + threadIdx.x;
    int b = blockIdx.y;
    __shared__ float q_s[HID];
    for (int i = threadIdx.x; i < HID; i += 256) q_s[i] = hidden[b*HID + i];
    __syncthreads();
    float acc = bk[h];
    #pragma unroll 8
    for (int k = 0; k < HID; k++)
        acc = fmaf(q_s[k], Wq[(size_t)k*HID + h], acc);
    g_qw[b*HID + h] = acc;
}

// ---------------- feat GEMM: warp-pair-autonomous pipeline -----------------
// 512 thr, 16 warps = 8 pairs (pair id wn, members wm 0/1 share 32 cols).
// Per pair: private 4-stage B ring (16k x 32n, stride 40 -> conflict-free),
// each warp cp.asyncs its own 8-k half, pairwise named barrier (id 1+wn, 64).
// A fragment-major (128 KB), read-only after one initial block sync.
// it = ncc*32 + kc: ncc (0..3) 256-col group, kc (0..31) 16-k chunk.
#define PB_ROW 40
#define PB_STG (16*PB_ROW*4)             // 2560 bytes per pair-stage
#define F_A   0
#define F_B   (64*512*4)                 // 131072
#define F_QW  (F_B + 8*4*PB_STG)         // 131072 + 81920 = 212992
#define F_V   (F_QW + HID*4)
#define F_SC  (F_V + HID*4)
#define FEAT_SMEM (F_SC + 64*4)          // 221440

__global__ void __launch_bounds__(512) k_feat9(const float* __restrict__ ann,
                                               const float* __restrict__ v_attn) {
    extern __shared__ char sm[];
    const uint32_t smb = smem_u32(sm);
    float* A_f  = (float*)(sm + F_A);
    float* qw_s = (float*)(sm + F_QW);
    float* v_s  = (float*)(sm + F_V);
    float* sc_s = (float*)(sm + F_SC);

    const int bx   = blockIdx.x;
    const int b    = bx >> 5;
    const int row0 = (bx & 31) * 64;
    const int tid  = threadIdx.x;
    const int lane = tid & 31;
    const int warp = tid >> 5;
    const int wm   = warp >> 3;       // 0..1 (pair member / 32-row half)
    const int wn   = warp & 7;        // 0..7 (pair id / 32-col slice)
    const int g    = lane >> 2;       // 0..7
    const int qt   = lane & 3;        // 0..3
    const int barid = 1 + wn;

    for (int i = tid; i < HID; i += 512) {
        qw_s[i] = g_qw[b*HID + i];
        v_s[i]  = v_attn[i];
    }
    if (tid < 64) sc_s[tid] = 0.f;

    // A tile -> fragment-major layout, tf32-rounded (RNA). One-time.
    {
        const float4* src = (const float4*)(ann + ((size_t)b * NK + row0) * KEY);
        for (int i = tid; i < 64*128; i += 512) {
            int r  = i >> 7;
            int k4 = i & 127;
            float4 v4 = src[i];
            v4.x = to_tf32(v4.x); v4.y = to_tf32(v4.y);
            v4.z = to_tf32(v4.z); v4.w = to_tf32(v4.w);
            int ko   = k4 >> 1;
            int half = k4 & 1;
            int rg   = r >> 4;
            int hi8  = (r >> 3) & 1;
            int gg   = r & 7;
            int slot = (half << 1) | hi8;
            float* base = A_f + (ko*4 + rg)*128;
            base[(gg*4 + 0)*4 + slot] = v4.x;
            base[(gg*4 + 1)*4 + slot] = v4.y;
            base[(gg*4 + 2)*4 + slot] = v4.z;
            base[(gg*4 + 3)*4 + slot] = v4.w;
        }
    }
    __syncthreads();   // A, qw, v, sc visible to all; last block-wide sync
                       // until the final score reduction.

    // per-warp issue: 8 k-rows x 32 cols of this pair's chunk
    const int lr = lane >> 2;            // 0..7 k-row within half
    const int lc = lane & 3;             // float4 pair selector
    auto issue = [&](int it) {
        int ncc = it >> 5, kc = it & 31, buf = it & 3;
        const float* src = g_wkR + (size_t)(kc*16 + wm*8 + lr)*HID + ncc*256 + wn*32;
        uint32_t dstbase = smb + F_B + (uint32_t)(wn*4 + buf)*PB_STG
                         + (uint32_t)((wm*8 + lr)*PB_ROW)*4;
        #pragma unroll
        for (int u = 0; u < 2; u++) {
            int c4 = lc*2 + u;
            asm volatile("cp.async.cg.shared.global [%0], [%1], 16;"
                         :: "r"(dstbase + c4*16), "l"(src + c4*4));
        }
        asm volatile("cp.async.commit_group;" ::: "memory");
    };

    issue(0); issue(1); issue(2);

    float rs[2][2] = {{0.f,0.f},{0.f,0.f}};
    float acc[2][4][4];
    const int rgbase = wm*2;

    for (int it = 0; it < 128; it++) {
        const int buf = it & 3;
        const int kc  = it & 31;
        if (it < 126)       asm volatile("cp.async.wait_group 2;" ::: "memory");
        else if (it == 126) asm volatile("cp.async.wait_group 1;" ::: "memory");
        else                asm volatile("cp.async.wait_group 0;" ::: "memory");
        asm volatile("bar.sync %0, 64;" :: "r"(barid) : "memory");
        if (it + 3 < 128) issue(it + 3);

        if (kc == 0) {
            #pragma unroll
            for (int mt = 0; mt < 2; mt++)
                #pragma unroll
                for (int nt = 0; nt < 4; nt++)
                    #pragma unroll
                    for (int i = 0; i < 4; i++) acc[mt][nt][i] = 0.f;
        }

        const float* Bst = (const float*)(sm + F_B + (wn*4 + buf)*PB_STG);

        float4 af[2][2];
        unsigned bf[2][4][2];
        #pragma unroll
        for (int kk = 0; kk < 2; kk++) {
            const int ko = kc*2 + kk;
            #pragma unroll
            for (int mt = 0; mt < 2; mt++)
                af[kk][mt] = *(const float4*)(A_f + ((ko*4 + rgbase + mt)*32 + lane)*4);
            #pragma unroll
            for (int nt = 0; nt < 4; nt++) {
                int cn = nt*8 + g;
                bf[kk][nt][0] = __float_as_uint(Bst[(kk*8 + qt)*PB_ROW + cn]);
                bf[kk][nt][1] = __float_as_uint(Bst[(kk*8 + qt + 4)*PB_ROW + cn]);
            }
        }
        #pragma unroll
        for (int kk = 0; kk < 2; kk++) {
            #pragma unroll
            for (int nt = 0; nt < 4; nt++) {
                #pragma unroll
                for (int mt = 0; mt < 2; mt++) {
                    asm volatile(
                        "mma.sync.aligned.m16n8k8.row.col.f32.tf32.tf32.f32 "
                        "{%0,%1,%2,%3}, {%4,%5,%6,%7}, {%8,%9}, {%0,%1,%2,%3};"
                        : "+f"(acc[mt][nt][0]), "+f"(acc[mt][nt][1]),
                          "+f"(acc[mt][nt][2]), "+f"(acc[mt][nt][3])
                        : "r"(__float_as_uint(af[kk][mt].x)),
                          "r"(__float_as_uint(af[kk][mt].y)),
                          "r"(__float_as_uint(af[kk][mt].z)),
                          "r"(__float_as_uint(af[kk][mt].w)),
                          "r"(bf[kk][nt][0]), "r"(bf[kk][nt][1]));
                }
            }
        }

        if (kc == 31) {
            const int ncc = it >> 5;
            #pragma unroll
            for (int mt = 0; mt < 2; mt++)
                #pragma unroll
                for (int nt = 0; nt < 4; nt++) {
                    int h0 = ncc*256 + wn*32 + nt*8 + qt*2;
                    float v0 = v_s[h0],     q0u = qw_s[h0];
                    float v1 = v_s[h0 + 1], q1u = qw_s[h0 + 1];
                    rs[mt][0] = fmaf(v0, tanhf(acc[mt][nt][0] + q0u), rs[mt][0]);
                    rs[mt][0] = fmaf(v1, tanhf(acc[mt][nt][1] + q1u), rs[mt][0]);
                    rs[mt][1] = fmaf(v0, tanhf(acc[mt][nt][2] + q0u), rs[mt][1]);
                    rs[mt][1] = fmaf(v1, tanhf(acc[mt][nt][3] + q1u), rs[mt][1]);
                }
        }
    }

    #pragma unroll
    for (int mt = 0; mt < 2; mt++)
        #pragma unroll
        for (int up = 0; up < 2; up++) {
            float p = rs[mt][up];
            p += __shfl_xor_sync(0xffffffffu, p, 1);
            p += __shfl_xor_sync(0xffffffffu, p, 2);
            if (qt == 0)
                atomicAdd(&sc_s[wm*32 + mt*16 + up*8 + g], p);
        }
    __syncthreads();
    if (tid < 64) g_scores[(size_t)b*NK + row0 + tid] = sc_s[tid];
}

// ---------------- softmax + emb copy ---------------------------------------
__global__ void __launch_bounds__(256) k_attn_sm(const int* __restrict__ ids,
                                                 const float* __restrict__ emb_table,
                                                 float* __restrict__ a_out) {
    int b = blockIdx.x;
    int tid = threadIdx.x;
    __shared__ float sc[NK];
    __shared__ float red[256];

    float m = -1e30f;
    for (int i = tid; i < NK; i += 256) {
        float v = g_scores[b*NK + i];
        sc[i] = v;
        m = fmaxf(m, v);
    }
    red[tid] = m; __syncthreads();
    for (int s = 128; s; s >>= 1) { if (tid < s) red[tid] = fmaxf(red[tid], red[tid+s]); __syncthreads(); }
    m = red[0]; __syncthreads();

    float sum = 0.f;
    for (int i = tid; i < NK; i += 256) { float e = expf(sc[i] - m); sc[i] = e; sum += e; }
    red[tid] = sum; __syncthreads();
    for (int s = 128; s; s >>= 1) { if (tid < s) red[tid] += red[tid+s]; __syncthreads(); }
    float inv = 1.f / red[0];
    __syncthreads();

    for (int i = tid; i < NK; i += 256)
        a_out[(size_t)b*NK + i] = sc[i] * inv;

    int id = ids[b];
    for (int k = tid; k < EMB; k += 256)
        g_x[b*(EMB+KEY) + k] = emb_table[(size_t)id*EMB + k];
}

// ---------------- context = a . ann ----------------------------------------
__global__ void __launch_bounds__(256) k_ctx(const float* __restrict__ ann,
                                             const float* __restrict__ a_out) {
    int b = blockIdx.x;
    int p = blockIdx.y;
    int tid = threadIdx.x;
    int c  = tid & 31;
    int rg = tid >> 5;
    __shared__ float part[8][33];

    const float* ab = ann + (size_t)b*NK*KEY + p*32 + c;
    const float* av = a_out + (size_t)b*NK;
    float acc = 0.f;
    for (int n = rg; n < NK; n += 8)
        acc = fmaf(av[n], ab[(size_t)n*KEY], acc);
    part[rg][c] = acc;
    __syncthreads();
    if (rg == 0) {
        float s = part[0][c] + part[1][c] + part[2][c] + part[3][c]
                + part[4][c] + part[5][c] + part[6][c] + part[7][c];
        g_x[b*(EMB+KEY) + EMB + p*32 + c] = s;
    }
}

// ---------------- shared tf32 GEMM body (template rounding) ----------------
#define L_ALD 68
#define L_BLD 68
#define L_ASTG (64*L_ALD*4)
#define L_BSTG (128*L_BLD*4)
#define L_STG  (L_ASTG + L_BSTG)
#define LOG_SMEM (3*L_STG)               // 156672

template<bool RND>
__device__ __forceinline__ void gemm_tc_body(const float* __restrict__ Amat,
                                             const float* __restrict__ W,
                                             int v0, int N, uint32_t smb, char* sm,
                                             float acc[2][4][4]) {
    const int tid = threadIdx.x;
    const int lane = tid & 31;
    const int warp = tid >> 5;
    const int wm = warp >> 2;
    const int wn = warp & 3;
    const int g  = lane >> 2;
    const int qt = lane & 3;

    auto rnd = [](float x) -> unsigned {
        if (RND) { unsigned r; asm("cvt.rna.tf32.f32 %0, %1;" : "=r"(r) : "f"(x)); return r; }
        return __float_as_uint(x);
    };

    auto issue = [&](int kc) {
        int buf = kc % 3;
        {
            const float* src = Amat + kc*64;
            #pragma unroll
            for (int u = 0; u < 4; u++) {
                int gi = tid + u*256;
                int r = gi >> 4, c4 = gi & 15;
                uint32_t dst = smb + buf*L_STG + (uint32_t)(r*L_ALD + c4*4)*4;
                const float* s = src + (size_t)r*HID + c4*4;
                asm volatile("cp.async.cg.shared.global [%0], [%1], 16;" :: "r"(dst), "l"(s));
            }
        }
        {
            #pragma unroll
            for (int u = 0; u < 8; u++) {
                int gi = tid + u*256;
                int r = gi >> 4, c4 = gi & 15;
                int v = v0 + r;
                uint32_t dst = smb + buf*L_STG + L_ASTG + (uint32_t)(r*L_BLD + c4*4)*4;
                const float* s = (v < N) ? (W + (size_t)v*HID + kc*64 + c4*4) : W;
                unsigned sz = (v < N) ? 16u : 0u;
                asm volatile("cp.async.cg.shared.global [%0], [%1], 16, %2;"
                             :: "r"(dst), "l"(s), "r"(sz));
            }
        }
        asm volatile("cp.async.commit_group;" ::: "memory");
    };

    issue(0); issue(1);

    #pragma unroll
    for (int mt = 0; mt < 2; mt++)
        #pragma unroll
        for (int nt = 0; nt < 4; nt++)
            #pragma unroll
            for (int i = 0; i < 4; i++) acc[mt][nt][i] = 0.f;

    for (int kc = 0; kc < 16; kc++) {
        const int buf = kc % 3;
        if (kc < 15) asm volatile("cp.async.wait_group 1;" ::: "memory");
        else         asm volatile("cp.async.wait_group 0;" ::: "memory");
        __syncthreads();

        const float* A_s = (const float*)(sm + buf*L_STG);
        const float* B_s = (const float*)(sm + buf*L_STG + L_ASTG);
        #pragma unroll
        for (int kk = 0; kk < 8; kk++) {
            const int ka = kk*8 + qt;
            unsigned a[2][4];
            #pragma unroll
            for (int mt = 0; mt < 2; mt++) {
                int r = wm*32 + mt*16 + g;
                a[mt][0] = rnd(A_s[r*L_ALD + ka]);
                a[mt][1] = rnd(A_s[(r+8)*L_ALD + ka]);
                a[mt][2] = rnd(A_s[r*L_ALD + ka + 4]);
                a[mt][3] = rnd(A_s[(r+8)*L_ALD + ka + 4]);
            }
            #pragma unroll
            for (int nt = 0; nt < 4; nt++) {
                int cn = wn*32 + nt*8 + g;
                unsigned b0 = rnd(B_s[cn*L_BLD + ka]);
                unsigned b1 = rnd(B_s[cn*L_BLD + ka + 4]);
                #pragma unroll
                for (int mt = 0; mt < 2; mt++) {
                    asm volatile(
                        "mma.sync.aligned.m16n8k8.row.col.f32.tf32.tf32.f32 "
                        "{%0,%1,%2,%3}, {%4,%5,%6,%7}, {%8,%9}, {%0,%1,%2,%3};"
                        : "+f"(acc[mt][nt][0]), "+f"(acc[mt][nt][1]),
                          "+f"(acc[mt][nt][2]), "+f"(acc[mt][nt][3])
                        : "r"(a[mt][0]), "r"(a[mt][1]), "r"(a[mt][2]), "r"(a[mt][3]),
                          "r"(b0), "r"(b1));
                }
            }
        }
        if (kc + 2 < 16) issue(kc + 2);
    }
}

// gi/gh GEMM combined: blockIdx.y selects (1: gh from hidden/W_hh, 0: gi).
// RNA rounding kept here — truncation caused the round-6 rel_err spike.
__global__ void __launch_bounds__(256) k_gru_tc(const float* __restrict__ hidden,
                                                const float* __restrict__ W_ih,
                                                const float* __restrict__ W_hh) {
    extern __shared__ char sm[];
    const uint32_t smb = smem_u32(sm);
    const int which = blockIdx.y;
    const float* Amat = which ? hidden : g_x;
    const float* W    = which ? W_hh   : W_ih;
    float*       C    = which ? g_gh   : g_gi;
    const int v0 = blockIdx.x * 128;

    float acc[2][4][4];
    gemm_tc_body<true>(Amat, W, v0, 3*HID, smb, sm, acc);

    const int lane = threadIdx.x & 31;
    const int warp = threadIdx.x >> 5;
    const int wm = warp >> 2, wn = warp & 3;
    const int g = lane >> 2, qt = lane & 3;
    #pragma unroll
    for (int mt = 0; mt < 2; mt++) {
        int r0 = wm*32 + mt*16 + g;
        #pragma unroll
        for (int nt = 0; nt < 4; nt++) {
            int c0 = v0 + wn*32 + nt*8 + qt*2;
            C[(size_t)r0*3*HID + c0]         = acc[mt][nt][0];
            C[(size_t)r0*3*HID + c0 + 1]     = acc[mt][nt][1];
            C[(size_t)(r0+8)*3*HID + c0]     = acc[mt][nt][2];
            C[(size_t)(r0+8)*3*HID + c0 + 1] = acc[mt][nt][3];
        }
    }
}

// logits GEMM (bias added). Truncation (no RNA) validated in round 5: 8.7e-5.
__global__ void __launch_bounds__(256) k_logits_tc10(const float* __restrict__ W_out,
                                                     const float* __restrict__ b_out,
                                                     float* __restrict__ logits) {
    extern __shared__ char sm[];
    const uint32_t smb = smem_u32(sm);
    const int v0 = blockIdx.x * 128;

    float acc[2][4][4];
    gemm_tc_body<false>(g_h, W_out, v0, VOCAB, smb, sm, acc);

    const int lane = threadIdx.x & 31;
    const int warp = threadIdx.x >> 5;
    const int wm = warp >> 2, wn = warp & 3;
    const int g = lane >> 2, qt = lane & 3;
    #pragma unroll
    for (int mt = 0; mt < 2; mt++) {
        int r0 = wm*32 + mt*16 + g;
        #pragma unroll
        for (int nt = 0; nt < 4; nt++) {
            int c0 = v0 + wn*32 + nt*8 + qt*2;
            if (c0 + 1 < VOCAB) {
                float bo0 = b_out[c0], bo1 = b_out[c0+1];
                logits[(size_t)r0*VOCAB + c0]         = acc[mt][nt][0] + bo0;
                logits[(size_t)r0*VOCAB + c0 + 1]     = acc[mt][nt][1] + bo1;
                logits[(size_t)(r0+8)*VOCAB + c0]     = acc[mt][nt][2] + bo0;
                logits[(size_t)(r0+8)*VOCAB + c0 + 1] = acc[mt][nt][3] + bo1;
            } else if (c0 < VOCAB) {
                float bo0 = b_out[c0];
                logits[(size_t)r0*VOCAB + c0]     = acc[mt][nt][0] + bo0;
                logits[(size_t)(r0+8)*VOCAB + c0] = acc[mt][nt][2] + bo0;
            }
        }
    }
}

// ---------------- GRU gates ------------------------------------------------
__global__ void __launch_bounds__(256) k_gates(const float* __restrict__ hidden,
                                               const float* __restrict__ b_ih,
                                               const float* __restrict__ b_hh,
                                               float* __restrict__ o_out) {
    int j = blockIdx.x * 256 + threadIdx.x;
    int b = blockIdx.y;
    float ir  = g_gi[b*3*HID + j]         + b_ih[j];
    float iz  = g_gi[b*3*HID + HID + j]   + b_ih[HID + j];
    float inn = g_gi[b*3*HID + 2*HID + j] + b_ih[2*HID + j];
    float hr  = g_gh[b*3*HID + j]         + b_hh[j];
    float hz  = g_gh[b*3*HID + HID + j]   + b_hh[HID + j];
    float hn  = g_gh[b*3*HID + 2*HID + j] + b_hh[2*HID + j];
    float r = 1.f / (1.f + expf(-(ir + hr)));
    float z = 1.f / (1.f + expf(-(iz + hz)));
    float n = tanhf(inn + r * hn);
    float q = hidden[b*HID + j];
    float h = (1.f - z) * n + z * q;
    g_h[b*HID + j]   = h;
    o_out[b*HID + j] = h;
}

// ---------------- split logsumexp ------------------------------------------
#define LSE_CH 6283            // ceil(VOCAB/8)
__global__ void __launch_bounds__(256) k_lse1(const float* __restrict__ logits) {
    int b = blockIdx.x, p = blockIdx.y, tid = threadIdx.x;
    __shared__ float red[256];
    const float* row = logits + (size_t)b*VOCAB;
    int start = p*LSE_CH;
    int end = start + LSE_CH; if (end > VOCAB) end = VOCAB;
    float m = -1e30f;
    for (int v = start + tid; v < end; v += 256) m = fmaxf(m, row[v]);
    red[tid] = m; __syncthreads();
    for (int s = 128; s; s >>= 1) { if (tid < s) red[tid] = fmaxf(red[tid], red[tid+s]); __syncthreads(); }
    m = red[0]; __syncthreads();
    float sum = 0.f;
    for (int v = start + tid; v < end; v += 256) sum += expf(row[v] - m);
    red[tid] = sum; __syncthreads();
    for (int s = 128; s; s >>= 1) { if (tid < s) red[tid] += red[tid+s]; __syncthreads(); }
    if (tid == 0) { g_pm[b*8 + p] = m; g_ps[b*8 + p] = red[0]; }
}

__global__ void __launch_bounds__(64) k_lse2() {
    int b = threadIdx.x;
    float m = -1e30f;
    #pragma unroll
    for (int p = 0; p < 8; p++) m = fmaxf(m, g_pm[b*8 + p]);
    float s = 0.f;
    #pragma unroll
    for (int p = 0; p < 8; p++) s += g_ps[b*8 + p] * expf(g_pm[b*8 + p] - m);
    g_lse[b] = m + logf(s);
}

__global__ void __launch_bounds__(256) k_sub(float* __restrict__ logp) {
    int v = blockIdx.x * 256 + threadIdx.x;
    int b = blockIdx.y;
    if (v < VOCAB) logp[(size_t)b*VOCAB + v] -= g_lse[b];
}

// ---------------- launcher -------------------------------------------------
extern "C" void kernel_launch(void* const* d_in, const int* in_sizes, int n_in,
                              void* d_out, int out_size) {
    const int*   ids    = (const int*)d_in[0];
    const float* hidden = (const float*)d_in[1];
    const float* ann    = (const float*)d_in[2];
    const float* emb    = (const float*)d_in[3];
    const float* Wk     = (const float*)d_in[4];
    const float* Wq     = (const float*)d_in[5];
    const float* bk     = (const float*)d_in[6];
    const float* v_attn = (const float*)d_in[7];
    const float* W_ih   = (const float*)d_in[8];
    const float* W_hh   = (const float*)d_in[9];
    const float* b_ih   = (const float*)d_in[10];
    const float* b_hh   = (const float*)d_in[11];
    const float* W_out  = (const float*)d_in[12];
    const float* b_out  = (const float*)d_in[13];

    float* out   = (float*)d_out;
    float* logp  = out;
    float* o_out = out + O_OFF;
    float* a_out = out + A_OFF;

    cudaFuncSetAttribute(k_feat9,       cudaFuncAttributeMaxDynamicSharedMemorySize, FEAT_SMEM);
    cudaFuncSetAttribute(k_gru_tc,      cudaFuncAttributeMaxDynamicSharedMemorySize, LOG_SMEM);
    cudaFuncSetAttribute(k_logits_tc10, cudaFuncAttributeMaxDynamicSharedMemorySize, LOG_SMEM);

    k_wkr        <<<(KEY*HID)/256, 256>>>(Wk);
    k_qw         <<<dim3(HID/256, B), 256>>>(hidden, Wq, bk);
    k_feat9      <<<(B*NK)/64, 512, FEAT_SMEM>>>(ann, v_attn);
    k_attn_sm    <<<B, 256>>>(ids, emb, a_out);
    k_ctx        <<<dim3(B, 16), 256>>>(ann, a_out);
    k_gru_tc     <<<dim3(3*HID/128, 2), 256, LOG_SMEM>>>(hidden, W_ih, W_hh);
    k_gates      <<<dim3(HID/256, B), 256>>>(hidden, b_ih, b_hh, o_out);
    k_logits_tc10<<<(VOCAB + 127)/128, 256, LOG_SMEM>>>(W_out, b_out, logp);
    k_lse1       <<<dim3(B, 8), 256>>>(logp);
    k_lse2       <<<1, 64>>>();
    k_sub        <<<dim3((VOCAB + 255)/256, B), 256>>>(logp);
}